// round 17
// baseline (speedup 1.0000x reference)
#include <cuda_runtime.h>

// QuantumConvLayer: out[:,2i]   = cos(q[2i]) * cos(pi*x[:,2i])
//                   out[:,2i+1] = out[:,2i]  * cos(q[2i+1] + pi*x[:,2i+1])
// Streaming HBM-bound: 256MB read + 256MB write, zero reuse.
//
// R17: keep the CONFIRMED sustained optimum (grid=4096, 64KB contiguous
// tile per direction per CTA; R13/R16: 80.13/80.32us) but repartition:
// TPB=512, CPT=4, in-place compute (44 regs -> 2 CTAs/SM resident).
// Same 32-warp/SM ceiling as R13, but 4 front-batched LDG.256 per thread
// = 128B in flight -> per-SM in-flight bytes DOUBLE vs R13 (64B, 1 CTA).
// CTA-count curve: 65536:82.4 | 8192:81.6 | 4096:80.1-80.3 | 2048:83.1.

#ifndef QC_PI
#define QC_PI 3.14159265358979323846f
#endif

#define TPB 512   // threads per block
#define CPT 4     // 8-float chunks per thread
#define TILE_CH (TPB * CPT)   // 2048 chunks (16384 floats = 64KB) per block

__device__ __forceinline__ void ldg256_ef(const float* p, float r[8])
{
    asm volatile("ld.global.nc.L2::evict_first.v8.f32 "
                 "{%0,%1,%2,%3,%4,%5,%6,%7}, [%8];"
                 : "=f"(r[0]), "=f"(r[1]), "=f"(r[2]), "=f"(r[3]),
                   "=f"(r[4]), "=f"(r[5]), "=f"(r[6]), "=f"(r[7])
                 : "l"(p));
}

__device__ __forceinline__ void stg256_ef(float* p, const float r[8])
{
    asm volatile("st.global.L2::evict_first.v8.f32 "
                 "[%0], {%1,%2,%3,%4,%5,%6,%7,%8};"
                 :: "l"(p),
                    "f"(r[0]), "f"(r[1]), "f"(r[2]), "f"(r[3]),
                    "f"(r[4]), "f"(r[5]), "f"(r[6]), "f"(r[7])
                 : "memory");
}

// compute in place: v[] becomes the output chunk
__device__ __forceinline__ void qc_chunk_ip(float v[8],
                                            float ca, float cb, float cc, float cd,
                                            float qay, float qaw, float qby, float qbw)
{
    v[0] = ca * __cosf(QC_PI * v[0]);
    v[1] = v[0] * __cosf(fmaf(QC_PI, v[1], qay));
    v[2] = cb * __cosf(QC_PI * v[2]);
    v[3] = v[2] * __cosf(fmaf(QC_PI, v[3], qaw));
    v[4] = cc * __cosf(QC_PI * v[4]);
    v[5] = v[4] * __cosf(fmaf(QC_PI, v[5], qby));
    v[6] = cd * __cosf(QC_PI * v[6]);
    v[7] = v[6] * __cosf(fmaf(QC_PI, v[7], qbw));
}

__global__ void __launch_bounds__(TPB)
qconv_kernel(const float* __restrict__ x,
             const float* __restrict__ q,
             float* __restrict__ out)
{
    int c0 = blockIdx.x * TILE_CH + threadIdx.x;   // chunks at +0,+TPB,+2TPB,+3TPB

    // chunk offsets are multiples of TPB=512 (even) -> shared row phase
    const float4* q4 = (const float4*)q;
    int ph = (c0 & 1) << 1;            // 0 or 2 (float4 index)
    float4 qa = __ldg(q4 + ph);        // q[8p .. 8p+3]
    float4 qb = __ldg(q4 + ph + 1);    // q[8p+4 .. 8p+7]

    float ca = __cosf(qa.x);
    float cb = __cosf(qa.z);
    float cc = __cosf(qb.x);
    float cd = __cosf(qb.z);

    // ALL four 256-bit loads front-batched: 128B in flight per thread
    float v0[8], v1[8], v2[8], v3[8];
    ldg256_ef(x + (size_t)(c0 + 0 * TPB) * 8, v0);
    ldg256_ef(x + (size_t)(c0 + 1 * TPB) * 8, v1);
    ldg256_ef(x + (size_t)(c0 + 2 * TPB) * 8, v2);
    ldg256_ef(x + (size_t)(c0 + 3 * TPB) * 8, v3);

    // compute in place, store as each chunk completes
    qc_chunk_ip(v0, ca, cb, cc, cd, qa.y, qa.w, qb.y, qb.w);
    stg256_ef(out + (size_t)(c0 + 0 * TPB) * 8, v0);

    qc_chunk_ip(v1, ca, cb, cc, cd, qa.y, qa.w, qb.y, qb.w);
    stg256_ef(out + (size_t)(c0 + 1 * TPB) * 8, v1);

    qc_chunk_ip(v2, ca, cb, cc, cd, qa.y, qa.w, qb.y, qb.w);
    stg256_ef(out + (size_t)(c0 + 2 * TPB) * 8, v2);

    qc_chunk_ip(v3, ca, cb, cc, cd, qa.y, qa.w, qb.y, qb.w);
    stg256_ef(out + (size_t)(c0 + 3 * TPB) * 8, v3);
}

extern "C" void kernel_launch(void* const* d_in, const int* in_sizes, int n_in,
                              void* d_out, int out_size)
{
    const float* x = (const float*)d_in[0];
    const float* q = (const float*)d_in[1];
    float* out     = (float*)d_out;

    int n_elems  = in_sizes[0];     // B * 16 = 67108864
    int n_chunks = n_elems >> 3;    // 8388608 chunks; divisible by TILE_CH=2048

    int blocks = n_chunks / TILE_CH;   // 4096, exact
    qconv_kernel<<<blocks, TPB>>>(x, q, out);
}